// round 6
// baseline (speedup 1.0000x reference)
#include <cuda_runtime.h>

// BaseEBM: 1M samples x 20 GD steps on scalar y through fixed
// 2->32->32->32->1 ReLU MLP (fwd+bwd per step). One thread = one sample.
//
// SPILL-PROOF ARCHITECTURE: only ONE 32-float register accumulator set is
// ever live (AC0..AC31, individually named). Vector handoffs between
// matvecs go through a per-thread shared-memory scratch column
// (scr[i*TPB+tid], conflict-free, same-thread RAW so no barriers needed).
// Peak live registers ~60-80 << 255 cap, so ptxas emits a 0-byte stack
// frame and the driver never materializes the ~8KB/thread local pool that
// tripped the harness memory check in rounds 1-5.

#define W 32
#define INNER_STEPS 20
#define INNER_LR 0.1f
#define TPB 128

#define APPLY32(M) \
    M(0)  M(1)  M(2)  M(3)  M(4)  M(5)  M(6)  M(7)  \
    M(8)  M(9)  M(10) M(11) M(12) M(13) M(14) M(15) \
    M(16) M(17) M(18) M(19) M(20) M(21) M(22) M(23) \
    M(24) M(25) M(26) M(27) M(28) M(29) M(30) M(31)

// AC0..AC31 += V * ROW[j]; ROW = 32 floats in shared, 16B aligned.
#define MVROW(ROW, V) do {                                                 \
    const float4* _r4 = reinterpret_cast<const float4*>(ROW);              \
    float4 _c0 = _r4[0], _c1 = _r4[1], _c2 = _r4[2], _c3 = _r4[3];         \
    float4 _c4 = _r4[4], _c5 = _r4[5], _c6 = _r4[6], _c7 = _r4[7];         \
    AC0  = fmaf(_c0.x, V, AC0 ); AC1  = fmaf(_c0.y, V, AC1 );              \
    AC2  = fmaf(_c0.z, V, AC2 ); AC3  = fmaf(_c0.w, V, AC3 );              \
    AC4  = fmaf(_c1.x, V, AC4 ); AC5  = fmaf(_c1.y, V, AC5 );              \
    AC6  = fmaf(_c1.z, V, AC6 ); AC7  = fmaf(_c1.w, V, AC7 );              \
    AC8  = fmaf(_c2.x, V, AC8 ); AC9  = fmaf(_c2.y, V, AC9 );              \
    AC10 = fmaf(_c2.z, V, AC10); AC11 = fmaf(_c2.w, V, AC11);              \
    AC12 = fmaf(_c3.x, V, AC12); AC13 = fmaf(_c3.y, V, AC13);              \
    AC14 = fmaf(_c3.z, V, AC14); AC15 = fmaf(_c3.w, V, AC15);              \
    AC16 = fmaf(_c4.x, V, AC16); AC17 = fmaf(_c4.y, V, AC17);              \
    AC18 = fmaf(_c4.z, V, AC18); AC19 = fmaf(_c4.w, V, AC19);              \
    AC20 = fmaf(_c5.x, V, AC20); AC21 = fmaf(_c5.y, V, AC21);              \
    AC22 = fmaf(_c5.z, V, AC22); AC23 = fmaf(_c5.w, V, AC23);              \
    AC24 = fmaf(_c6.x, V, AC24); AC25 = fmaf(_c6.y, V, AC25);              \
    AC26 = fmaf(_c6.z, V, AC26); AC27 = fmaf(_c6.w, V, AC27);              \
    AC28 = fmaf(_c7.x, V, AC28); AC29 = fmaf(_c7.y, V, AC29);              \
    AC30 = fmaf(_c7.z, V, AC30); AC31 = fmaf(_c7.w, V, AC31);              \
} while (0)

__global__ __launch_bounds__(TPB) void BaseEBM_kernel(
    const float* __restrict__ gX,
    const float* __restrict__ gW0,   // [32,2]
    const float* __restrict__ gB0,   // [32]
    const float* __restrict__ gW1,   // [32,32]
    const float* __restrict__ gB1,   // [32]
    const float* __restrict__ gW2,   // [32,32]
    const float* __restrict__ gB2,   // [32]
    const float* __restrict__ gW3,   // [32]
    const float* __restrict__ gYM,   // [1]
    float* __restrict__ gOUT,
    int n) {
    // fw1[i*32+j]=W1[j][i], fw2[i*32+j]=W2[j][i]  (forward; j contiguous)
    // bw2[i*32+j]=W2[i][j], bw1[i*32+j]=W1[i][j]  (backward transposes)
    __shared__ alignas(16) float s_fw1[W * W];
    __shared__ alignas(16) float s_fw2[W * W];
    __shared__ alignas(16) float s_bw2[W * W];
    __shared__ alignas(16) float s_bw1[W * W];
    __shared__ alignas(16) float s_w0x[W];
    __shared__ alignas(16) float s_w0y[W];
    __shared__ alignas(16) float s_b0[W];
    __shared__ alignas(16) float s_b1[W];
    __shared__ alignas(16) float s_b2[W];
    __shared__ alignas(16) float s_w3[W];
    __shared__ float scr[W * TPB];   // per-thread scratch column

    const int tid = threadIdx.x;
#pragma unroll
    for (int k = 0; k < (W * W) / TPB; k++) {
        int e = k * TPB + tid;
        int i = e >> 5, j = e & 31;
        s_fw1[e] = gW1[j * W + i];
        s_fw2[e] = gW2[j * W + i];
        s_bw2[e] = gW2[e];
        s_bw1[e] = gW1[e];
    }
    if (tid < W) {
        s_w0x[tid] = gW0[2 * tid + 0];
        s_w0y[tid] = gW0[2 * tid + 1];
        s_b0[tid]  = gB0[tid];
        s_b1[tid]  = gB1[tid];
        s_b2[tid]  = gB2[tid];
        s_w3[tid]  = gW3[tid];
    }
    __syncthreads();

    const int idx = blockIdx.x * TPB + tid;
    if (idx >= n) return;

    const float x = gX[idx];
    float y = gYM[0];

    float AC0, AC1, AC2, AC3, AC4, AC5, AC6, AC7;
    float AC8, AC9, AC10, AC11, AC12, AC13, AC14, AC15;
    float AC16, AC17, AC18, AC19, AC20, AC21, AC22, AC23;
    float AC24, AC25, AC26, AC27, AC28, AC29, AC30, AC31;

#pragma unroll 1
    for (int s = 0; s < INNER_STEPS; s++) {
        unsigned m0 = 0u, m1 = 0u;

        // ---- layer 0 fused into layer-1 forward: AC = b1 + fw1^T relu(pre0)
#define INIT_B1(i) AC##i = s_b1[i];
        APPLY32(INIT_B1)
#undef INIT_B1
#define L0L1(i) {                                                          \
        float pre = fmaf(y, s_w0y[i], fmaf(x, s_w0x[i], s_b0[i]));         \
        m0 |= (pre > 0.0f) ? (1u << i) : 0u;                               \
        float h = fmaxf(pre, 0.0f);                                        \
        MVROW(s_fw1 + i * 32, h); }
        APPLY32(L0L1)
#undef L0L1

        // ---- AC = pre1. Spill h1=relu(pre1) to scratch, record m1.
#define ST_H1(i) {                                                         \
        m1 |= (AC##i > 0.0f) ? (1u << i) : 0u;                             \
        scr[i * TPB + tid] = fmaxf(AC##i, 0.0f); }
        APPLY32(ST_H1)
#undef ST_H1

        // ---- layer-2 forward: AC = b2 + fw2^T h1(scratch)
#define INIT_B2(i) AC##i = s_b2[i];
        APPLY32(INIT_B2)
#undef INIT_B2
#define L2F(i) { float v = scr[i * TPB + tid]; MVROW(s_fw2 + i * 32, v); }
        APPLY32(L2F)
#undef L2F

        // ---- AC = pre2. g2_i = (pre2_i>0)? w3_i : 0 -> scratch.
#define ST_G2(i) scr[i * TPB + tid] = (AC##i > 0.0f) ? s_w3[i] : 0.0f;
        APPLY32(ST_G2)
#undef ST_G2

        // ---- AC = bw2^T g2(scratch)
#define ZERO_AC(i) AC##i = 0.0f;
        APPLY32(ZERO_AC)
#define BW2(i) { float v = scr[i * TPB + tid]; MVROW(s_bw2 + i * 32, v); }
        APPLY32(BW2)
#undef BW2

        // ---- AC = g1raw. g1_i = m1-masked -> scratch.
#define ST_G1(i) scr[i * TPB + tid] = (m1 & (1u << i)) ? AC##i : 0.0f;
        APPLY32(ST_G1)
#undef ST_G1

        // ---- AC = bw1^T g1(scratch)
        APPLY32(ZERO_AC)
#undef ZERO_AC
#define BW1(i) { float v = scr[i * TPB + tid]; MVROW(s_bw1 + i * 32, v); }
        APPLY32(BW1)
#undef BW1

        // ---- dy = sum_k (pre0_k>0 ? w0y_k : 0) * g0raw_k
        float dy = 0.0f;
#define DYM(i) {                                                           \
        float wm = (m0 & (1u << i)) ? s_w0y[i] : 0.0f;                     \
        dy = fmaf(wm, AC##i, dy); }
        APPLY32(DYM)
#undef DYM

        y = fmaf(-INNER_LR, dy, y);
    }

    gOUT[idx] = y;
}

extern "C" void kernel_launch(void* const* d_in, const int* in_sizes, int n_in,
                              void* d_out, int out_size) {
    const float* x  = (const float*)d_in[0];
    const float* w0 = (const float*)d_in[1];
    const float* b0 = (const float*)d_in[2];
    const float* w1 = (const float*)d_in[3];
    const float* b1 = (const float*)d_in[4];
    const float* w2 = (const float*)d_in[5];
    const float* b2 = (const float*)d_in[6];
    const float* w3 = (const float*)d_in[7];
    const float* ymean = (const float*)d_in[9];  // d_in[8] = b3 (unused)
    float* out = (float*)d_out;

    int n = in_sizes[0];
    int blocks = (n + TPB - 1) / TPB;
    BaseEBM_kernel<<<blocks, TPB>>>(x, w0, b0, w1, b1, w2, b2, w3, ymean, out, n);
}